// round 4
// baseline (speedup 1.0000x reference)
#include <cuda_runtime.h>
#include <cstddef>

#define BATCH   64
#define NCAPS   32
#define NROUTES 2048
#define INDIM   16
#define OUTDIM  32
#define NITERS  3
#define THREADS 1024
#define NWARPS  (THREADS / 32)

// SMEM layout (floats):
//   sp[1024][33]   : priors for one half of the routes (33-stride pad -> conflict-free)
//   Vsh[32], sred[32], wred[32], wvec[32*32], scal[8]
#define SP_STRIDE 33
#define OFF_SP    0
#define OFF_VSH   (1024 * SP_STRIDE)
#define OFF_SRED  (OFF_VSH + 32)
#define OFF_WRED  (OFF_SRED + 32)
#define OFF_WVEC  (OFF_WRED + 32)
#define OFF_SCAL  (OFF_WVEC + NWARPS * 32)
#define SMEM_FLOATS (OFF_SCAL + 8)
#define SMEM_BYTES  (SMEM_FLOATS * 4)

// Quad-route warp scheme: lane l -> route (r4 + l/8), output cols 4*(l%8)..+3.
// Every W load is a coalesced LDG.128; each lane accumulates its 4 columns
// over all 16 i's privately (no cross-lane reduction).
__device__ __forceinline__ void quad_routes(const float* __restrict__ x,
                                            const float* __restrict__ W,
                                            int b, int c, int r4,
                                            int rsub, int c4,
                                            float acc[4])
{
    const int r = r4 + rsub;
    const float4* xr = reinterpret_cast<const float4*>(x + ((size_t)b * NROUTES + r) * INDIM);
    const float4* wr = reinterpret_cast<const float4*>(
        W + ((size_t)c * NROUTES + r) * (INDIM * OUTDIM)) + c4;  // stride per i: 8 float4

    float4 xq0 = __ldg(xr + 0);
    float4 xq1 = __ldg(xr + 1);
    float4 xq2 = __ldg(xr + 2);
    float4 xq3 = __ldg(xr + 3);
    float xs[INDIM] = { xq0.x, xq0.y, xq0.z, xq0.w,
                        xq1.x, xq1.y, xq1.z, xq1.w,
                        xq2.x, xq2.y, xq2.z, xq2.w,
                        xq3.x, xq3.y, xq3.z, xq3.w };

    acc[0] = acc[1] = acc[2] = acc[3] = 0.f;

#pragma unroll
    for (int g = 0; g < 4; g++) {
        float4 w0 = __ldg(wr + (g * 4 + 0) * 8);
        float4 w1 = __ldg(wr + (g * 4 + 1) * 8);
        float4 w2 = __ldg(wr + (g * 4 + 2) * 8);
        float4 w3 = __ldg(wr + (g * 4 + 3) * 8);
        float x0 = xs[g * 4 + 0], x1 = xs[g * 4 + 1];
        float x2 = xs[g * 4 + 2], x3 = xs[g * 4 + 3];
        acc[0] = fmaf(x0, w0.x, acc[0]); acc[1] = fmaf(x0, w0.y, acc[1]);
        acc[2] = fmaf(x0, w0.z, acc[2]); acc[3] = fmaf(x0, w0.w, acc[3]);
        acc[0] = fmaf(x1, w1.x, acc[0]); acc[1] = fmaf(x1, w1.y, acc[1]);
        acc[2] = fmaf(x1, w1.z, acc[2]); acc[3] = fmaf(x1, w1.w, acc[3]);
        acc[0] = fmaf(x2, w2.x, acc[0]); acc[1] = fmaf(x2, w2.y, acc[1]);
        acc[2] = fmaf(x2, w2.z, acc[2]); acc[3] = fmaf(x2, w2.w, acc[3]);
        acc[0] = fmaf(x3, w3.x, acc[0]); acc[1] = fmaf(x3, w3.y, acc[1]);
        acc[2] = fmaf(x3, w3.z, acc[2]); acc[3] = fmaf(x3, w3.w, acc[3]);
    }
}

__global__ void __launch_bounds__(THREADS, 1)
caps_route_kernel(const float* __restrict__ x,
                  const float* __restrict__ W,
                  float* __restrict__ out)
{
    extern __shared__ float sm[];
    float* sp   = sm + OFF_SP;
    float* Vsh  = sm + OFF_VSH;
    float* sred = sm + OFF_SRED;
    float* wred = sm + OFF_WRED;
    float* wvec = sm + OFF_WVEC;
    float* scal = sm + OFF_SCAL;

    const int t    = threadIdx.x;
    const int lane = t & 31;
    const int wid  = t >> 5;
    const int rsub = lane >> 3;   // 0..3 : route within quad
    const int c4   = lane & 7;    // 0..7 : float4 column group
    const int b    = blockIdx.x & (BATCH - 1);
    const int c    = blockIdx.x >> 6;

    if (t < 32) Vsh[t] = 0.f;

    // ---------------- Phase 1a: routes 0..1023 (warp w -> 8 quads) ----------------
    {
        const int base = wid * 32;
#pragma unroll 2
        for (int j = 0; j < 32; j += 4) {
            float acc[4];
            quad_routes(x, W, b, c, base + j, rsub, c4, acc);
            float* row = sp + (size_t)(base + j + rsub) * SP_STRIDE + c4 * 4;
            row[0] = acc[0]; row[1] = acc[1]; row[2] = acc[2]; row[3] = acc[3];
        }
    }
    __syncthreads();

    // Each thread pulls its register row (route t) out of SMEM.
    float accA[OUTDIM];
    {
        const float* rA = sp + (size_t)t * SP_STRIDE;
#pragma unroll
        for (int o = 0; o < OUTDIM; o++) accA[o] = rA[o];
    }
    __syncthreads();

    // ---------------- Phase 1b: routes 1024..2047 overwrite SMEM ----------------
    {
        const int base = wid * 32;
#pragma unroll 2
        for (int j = 0; j < 32; j += 4) {
            float acc[4];
            quad_routes(x, W, b, c, 1024 + base + j, rsub, c4, acc);
            float* row = sp + (size_t)(base + j + rsub) * SP_STRIDE + c4 * 4;
            row[0] = acc[0]; row[1] = acc[1]; row[2] = acc[2]; row[3] = acc[3];
        }
    }
    __syncthreads();

    const float* rowC = sp + (size_t)t * SP_STRIDE;   // route 1024+t

    // ---------------- Phase 2: dynamic routing (B_k[n] == p_n . sum_j v_j) ----------------
    for (int it = 0; it < NITERS; it++) {
        float p0, p1;
        if (it == 0) {
            p0 = p1 = 1.0f / (float)NROUTES;
        } else {
            float l0 = 0.f, l1 = 0.f;
#pragma unroll
            for (int o = 0; o < OUTDIM; o++) {
                float v = Vsh[o];
                l0 += accA[o] * v;
                l1 += rowC[o] * v;
            }
            float m = fmaxf(l0, l1);
#pragma unroll
            for (int s = 16; s; s >>= 1) m = fmaxf(m, __shfl_xor_sync(0xffffffffu, m, s));
            if (lane == 0) wred[wid] = m;
            __syncthreads();
            if (wid == 0) {
                float mm = wred[lane];
#pragma unroll
                for (int s = 16; s; s >>= 1) mm = fmaxf(mm, __shfl_xor_sync(0xffffffffu, mm, s));
                if (lane == 0) scal[0] = mm;
            }
            __syncthreads();
            const float bmax = scal[0];

            float e0 = __expf(l0 - bmax);
            float e1 = __expf(l1 - bmax);
            float zs = e0 + e1;
#pragma unroll
            for (int s = 16; s; s >>= 1) zs += __shfl_xor_sync(0xffffffffu, zs, s);
            if (lane == 0) wred[wid] = zs;
            __syncthreads();
            if (wid == 0) {
                float zz = wred[lane];
#pragma unroll
                for (int s = 16; s; s >>= 1) zz += __shfl_xor_sync(0xffffffffu, zz, s);
                if (lane == 0) scal[1] = zz;
            }
            __syncthreads();
            const float invZ = 1.0f / scal[1];
            p0 = e0 * invZ; p1 = e1 * invZ;
        }

        // s = sum_n probs_n * p_n : chunked (4 x 8) shuffle tree to cap live regs
#pragma unroll
        for (int ch = 0; ch < 4; ch++) {
            float ps[8];
#pragma unroll
            for (int o = 0; o < 8; o++) {
                int oo = ch * 8 + o;
                ps[o] = p0 * accA[oo] + p1 * rowC[oo];
            }
#pragma unroll
            for (int s = 16; s; s >>= 1) {
#pragma unroll
                for (int o = 0; o < 8; o++)
                    ps[o] += __shfl_xor_sync(0xffffffffu, ps[o], s);
            }
            if (lane == 0) {
#pragma unroll
                for (int o = 0; o < 8; o++) wvec[wid * 32 + ch * 8 + o] = ps[o];
            }
        }
        __syncthreads();
        if (t < 32) {
            float sv = 0.f;
#pragma unroll
            for (int w = 0; w < NWARPS; w++) sv += wvec[w * 32 + t];
            sred[t] = sv;
        }
        __syncthreads();

        if (t < 32) {
            float nr = 0.f;
#pragma unroll
            for (int o = 0; o < OUTDIM; o++) { float sv = sred[o]; nr += sv * sv; }
            float scale = (nr / (1.0f + nr)) * rsqrtf(nr);
            float v = scale * sred[t];
            Vsh[t] += v;
            if (it == NITERS - 1)
                out[((size_t)b * NCAPS + c) * OUTDIM + t] = v;
        }
        __syncthreads();
    }
}

extern "C" void kernel_launch(void* const* d_in, const int* in_sizes, int n_in,
                              void* d_out, int out_size)
{
    const float* x = (const float*)d_in[0];         // [64, 2048, 16]
    const float* W = (const float*)d_in[1];         // [32, 2048, 16, 32]
    float* out = (float*)d_out;                     // [64, 32, 32]

    cudaFuncSetAttribute(caps_route_kernel,
                         cudaFuncAttributeMaxDynamicSharedMemorySize, SMEM_BYTES);

    dim3 grid(BATCH * NCAPS);   // bid = c*64 + b  (same-c CTAs co-resident for L2 W reuse)
    caps_route_kernel<<<grid, THREADS, SMEM_BYTES>>>(x, W, out);
}